// round 1
// baseline (speedup 1.0000x reference)
#include <cuda_runtime.h>

// Global accumulator for sum(change) — double to make the 16M-element sum
// rounding-error-free relative to the 1e-3 tolerance.
__device__ double g_sum;

__global__ void k_zero() { g_sum = 0.0; }

// diff[i] = (g(i-3) - g(i+2)) / 5, zero outside [0,n); change[i] = diff^2 (i>=1), change[0]=0.

__global__ __launch_bounds__(256) void k_pass1(const float* __restrict__ f, long long n) {
    long long i = ((long long)blockIdx.x * blockDim.x + threadIdx.x) * 4;
    float acc = 0.0f;
    if (i + 3 < n) {
        float4 c = __ldg(reinterpret_cast<const float4*>(f + i));
        float m3 = (i >= 3) ? __ldg(f + i - 3) : 0.0f;
        float m2 = (i >= 2) ? __ldg(f + i - 2) : 0.0f;
        float m1 = (i >= 1) ? __ldg(f + i - 1) : 0.0f;
        float p4 = (i + 4 < n) ? __ldg(f + i + 4) : 0.0f;
        float p5 = (i + 5 < n) ? __ldg(f + i + 5) : 0.0f;

        float d0 = (m3  - c.z) * 0.2f;
        float d1 = (m2  - c.w) * 0.2f;
        float d2 = (m1  - p4 ) * 0.2f;
        float d3 = (c.x - p5 ) * 0.2f;

        float c0 = (i == 0) ? 0.0f : d0 * d0;
        acc = c0 + d1 * d1 + d2 * d2 + d3 * d3;
    } else if (i < n) {
        // scalar tail (not hit for n % 4 == 0, kept for safety)
        for (long long k = i; k < n; k++) {
            float l = (k >= 3) ? __ldg(f + k - 3) : 0.0f;
            float r = (k + 2 < n) ? __ldg(f + k + 2) : 0.0f;
            float d = (l - r) * 0.2f;
            if (k != 0) acc += d * d;
        }
    }

    // warp reduce
    #pragma unroll
    for (int o = 16; o > 0; o >>= 1)
        acc += __shfl_down_sync(0xffffffffu, acc, o);

    __shared__ float smem[8];
    int lane = threadIdx.x & 31;
    int warp = threadIdx.x >> 5;
    if (lane == 0) smem[warp] = acc;
    __syncthreads();
    if (threadIdx.x == 0) {
        float b = 0.0f;
        #pragma unroll
        for (int j = 0; j < 8; j++) b += smem[j];
        atomicAdd(&g_sum, (double)b);
    }
}

__global__ __launch_bounds__(256) void k_pass2(const float* __restrict__ f,
                                               float* __restrict__ out, long long n) {
    long long i = ((long long)blockIdx.x * blockDim.x + threadIdx.x) * 4;
    if (i >= n) return;
    float invS = (float)(1.0 / g_sum);

    if (i + 3 < n) {
        float4 c = __ldg(reinterpret_cast<const float4*>(f + i));
        float m3 = (i >= 3) ? __ldg(f + i - 3) : 0.0f;
        float m2 = (i >= 2) ? __ldg(f + i - 2) : 0.0f;
        float m1 = (i >= 1) ? __ldg(f + i - 1) : 0.0f;
        float p4 = (i + 4 < n) ? __ldg(f + i + 4) : 0.0f;
        float p5 = (i + 5 < n) ? __ldg(f + i + 5) : 0.0f;

        float d0 = (m3  - c.z) * 0.2f;
        float d1 = (m2  - c.w) * 0.2f;
        float d2 = (m1  - p4 ) * 0.2f;
        float d3 = (c.x - p5 ) * 0.2f;

        float c0 = (i == 0) ? 0.0f : d0 * d0 * invS;
        float c1 = d1 * d1 * invS;
        float c2 = d2 * d2 * invS;
        float c3 = d3 * d3 * invS;

        float t0 = 1.0f - c0, t1 = 1.0f - c1, t2 = 1.0f - c2, t3 = 1.0f - c3;
        // t^5 = (t^2)^2 * t
        float q0 = t0 * t0, q1 = t1 * t1, q2 = t2 * t2, q3 = t3 * t3;
        float4 o;
        o.x = q0 * q0 * t0 * c.x;
        o.y = q1 * q1 * t1 * c.y;
        o.z = q2 * q2 * t2 * c.z;
        o.w = q3 * q3 * t3 * c.w;
        *reinterpret_cast<float4*>(out + i) = o;
    } else {
        for (long long k = i; k < n; k++) {
            float l = (k >= 3) ? __ldg(f + k - 3) : 0.0f;
            float r = (k + 2 < n) ? __ldg(f + k + 2) : 0.0f;
            float d = (l - r) * 0.2f;
            float ch = (k == 0) ? 0.0f : d * d * invS;
            float t = 1.0f - ch;
            float q = t * t;
            out[k] = q * q * t * __ldg(f + k);
        }
    }
}

extern "C" void kernel_launch(void* const* d_in, const int* in_sizes, int n_in,
                              void* d_out, int out_size) {
    const float* f = (const float*)d_in[0];
    float* out = (float*)d_out;
    long long n = (long long)in_sizes[0];

    long long nvec = (n + 3) / 4;               // elements handled 4/thread
    int threads = 256;
    long long blocks = (nvec + threads - 1) / threads;

    k_zero<<<1, 1>>>();
    k_pass1<<<(unsigned)blocks, threads>>>(f, n);
    k_pass2<<<(unsigned)blocks, threads>>>(f, out, n);
}

// round 2
// speedup vs baseline: 1.9587x; 1.9587x over previous
#include <cuda_runtime.h>

// diff[k] = (g(k-3) - g(k+2)) / 5 with zero-padding outside [0,n)
// change[k] = diff[k]^2 for k>=1, change[0] = 0
// out[k] = (1 - change[k]/S)^5 * f[k],  S = sum(change)

#define TPB 256
#define VPT 4                 // float4 vectors per thread
#define ELEMS_PER_BLOCK (TPB * VPT * 4)   // 4096
#define MAX_BLOCKS 16384

__device__ float g_part[MAX_BLOCKS];
__device__ float g_invS;

// ---------------------------------------------------------------- pass 1
__global__ __launch_bounds__(TPB) void k_pass1(const float* __restrict__ f, int n) {
    const int tid  = threadIdx.x;
    const int bid  = blockIdx.x;
    const int base = bid * ELEMS_PER_BLOCK;
    const bool interior = (bid > 0) && (base + ELEMS_PER_BLOCK + 5 <= n);

    float acc = 0.0f;

    if (interior) {
        // branch-free fast path: all halo accesses in range, k>=1 guaranteed
        #pragma unroll
        for (int j = 0; j < VPT; j++) {
            const int v = base + j * (TPB * 4) + tid * 4;
            float4 c = __ldg(reinterpret_cast<const float4*>(f + v));
            float m3 = __ldg(f + v - 3);
            float m2 = __ldg(f + v - 2);
            float m1 = __ldg(f + v - 1);
            float p4 = __ldg(f + v + 4);
            float p5 = __ldg(f + v + 5);
            float d0 = (m3  - c.z) * 0.2f;
            float d1 = (m2  - c.w) * 0.2f;
            float d2 = (m1  - p4 ) * 0.2f;
            float d3 = (c.x - p5 ) * 0.2f;
            acc += d0 * d0 + d1 * d1 + d2 * d2 + d3 * d3;
        }
    } else {
        #pragma unroll
        for (int j = 0; j < VPT; j++) {
            const int v = base + j * (TPB * 4) + tid * 4;
            if (v + 3 < n) {
                float4 c = __ldg(reinterpret_cast<const float4*>(f + v));
                float m3 = (v >= 3)     ? __ldg(f + v - 3) : 0.0f;
                float m2 = (v >= 2)     ? __ldg(f + v - 2) : 0.0f;
                float m1 = (v >= 1)     ? __ldg(f + v - 1) : 0.0f;
                float p4 = (v + 4 < n)  ? __ldg(f + v + 4) : 0.0f;
                float p5 = (v + 5 < n)  ? __ldg(f + v + 5) : 0.0f;
                float d0 = (m3  - c.z) * 0.2f;
                float d1 = (m2  - c.w) * 0.2f;
                float d2 = (m1  - p4 ) * 0.2f;
                float d3 = (c.x - p5 ) * 0.2f;
                float c0 = (v == 0) ? 0.0f : d0 * d0;
                acc += c0 + d1 * d1 + d2 * d2 + d3 * d3;
            } else if (v < n) {
                for (int k = v; k < n; k++) {
                    float l = (k >= 3)    ? __ldg(f + k - 3) : 0.0f;
                    float r = (k + 2 < n) ? __ldg(f + k + 2) : 0.0f;
                    float d = (l - r) * 0.2f;
                    if (k != 0) acc += d * d;
                }
            }
        }
    }

    // warp reduce
    #pragma unroll
    for (int o = 16; o > 0; o >>= 1)
        acc += __shfl_down_sync(0xffffffffu, acc, o);

    __shared__ float smem[TPB / 32];
    const int lane = tid & 31;
    const int warp = tid >> 5;
    if (lane == 0) smem[warp] = acc;
    __syncthreads();
    if (tid == 0) {
        float b = 0.0f;
        #pragma unroll
        for (int w = 0; w < TPB / 32; w++) b += smem[w];
        g_part[bid] = b;   // plain overwrite: deterministic across graph replays
    }
}

// ---------------------------------------------------------------- sum
__global__ void k_sum(int nblocks) {
    __shared__ double smem[32];
    double acc = 0.0;
    for (int i = threadIdx.x; i < nblocks; i += blockDim.x)
        acc += (double)g_part[i];
    #pragma unroll
    for (int o = 16; o > 0; o >>= 1)
        acc += __shfl_down_sync(0xffffffffu, acc, o);
    const int lane = threadIdx.x & 31;
    const int warp = threadIdx.x >> 5;
    if (lane == 0) smem[warp] = acc;
    __syncthreads();
    if (threadIdx.x == 0) {
        double s = 0.0;
        const int nw = blockDim.x / 32;
        for (int w = 0; w < nw; w++) s += smem[w];
        g_invS = (float)(1.0 / s);
    }
}

// ---------------------------------------------------------------- pass 2
__global__ __launch_bounds__(TPB) void k_pass2(const float* __restrict__ f,
                                               float* __restrict__ out, int n) {
    const int tid  = threadIdx.x;
    const int bid  = blockIdx.x;
    const int base = bid * ELEMS_PER_BLOCK;
    const bool interior = (bid > 0) && (base + ELEMS_PER_BLOCK + 5 <= n);
    const float invS = g_invS;

    if (interior) {
        #pragma unroll
        for (int j = 0; j < VPT; j++) {
            const int v = base + j * (TPB * 4) + tid * 4;
            float4 c = __ldg(reinterpret_cast<const float4*>(f + v));
            float m3 = __ldg(f + v - 3);
            float m2 = __ldg(f + v - 2);
            float m1 = __ldg(f + v - 1);
            float p4 = __ldg(f + v + 4);
            float p5 = __ldg(f + v + 5);
            float d0 = (m3  - c.z) * 0.2f;
            float d1 = (m2  - c.w) * 0.2f;
            float d2 = (m1  - p4 ) * 0.2f;
            float d3 = (c.x - p5 ) * 0.2f;
            float t0 = 1.0f - d0 * d0 * invS;
            float t1 = 1.0f - d1 * d1 * invS;
            float t2 = 1.0f - d2 * d2 * invS;
            float t3 = 1.0f - d3 * d3 * invS;
            float q0 = t0 * t0, q1 = t1 * t1, q2 = t2 * t2, q3 = t3 * t3;
            float4 o;
            o.x = q0 * q0 * t0 * c.x;
            o.y = q1 * q1 * t1 * c.y;
            o.z = q2 * q2 * t2 * c.z;
            o.w = q3 * q3 * t3 * c.w;
            __stcs(reinterpret_cast<float4*>(out + v), o);
        }
    } else {
        #pragma unroll
        for (int j = 0; j < VPT; j++) {
            const int v = base + j * (TPB * 4) + tid * 4;
            if (v + 3 < n) {
                float4 c = __ldg(reinterpret_cast<const float4*>(f + v));
                float m3 = (v >= 3)    ? __ldg(f + v - 3) : 0.0f;
                float m2 = (v >= 2)    ? __ldg(f + v - 2) : 0.0f;
                float m1 = (v >= 1)    ? __ldg(f + v - 1) : 0.0f;
                float p4 = (v + 4 < n) ? __ldg(f + v + 4) : 0.0f;
                float p5 = (v + 5 < n) ? __ldg(f + v + 5) : 0.0f;
                float d0 = (m3  - c.z) * 0.2f;
                float d1 = (m2  - c.w) * 0.2f;
                float d2 = (m1  - p4 ) * 0.2f;
                float d3 = (c.x - p5 ) * 0.2f;
                float c0 = (v == 0) ? 0.0f : d0 * d0 * invS;
                float t0 = 1.0f - c0;
                float t1 = 1.0f - d1 * d1 * invS;
                float t2 = 1.0f - d2 * d2 * invS;
                float t3 = 1.0f - d3 * d3 * invS;
                float q0 = t0 * t0, q1 = t1 * t1, q2 = t2 * t2, q3 = t3 * t3;
                float4 o;
                o.x = q0 * q0 * t0 * c.x;
                o.y = q1 * q1 * t1 * c.y;
                o.z = q2 * q2 * t2 * c.z;
                o.w = q3 * q3 * t3 * c.w;
                __stcs(reinterpret_cast<float4*>(out + v), o);
            } else if (v < n) {
                for (int k = v; k < n; k++) {
                    float l = (k >= 3)    ? __ldg(f + k - 3) : 0.0f;
                    float r = (k + 2 < n) ? __ldg(f + k + 2) : 0.0f;
                    float d = (l - r) * 0.2f;
                    float ch = (k == 0) ? 0.0f : d * d * invS;
                    float t = 1.0f - ch;
                    float q = t * t;
                    out[k] = q * q * t * __ldg(f + k);
                }
            }
        }
    }
}

// ---------------------------------------------------------------- launch
extern "C" void kernel_launch(void* const* d_in, const int* in_sizes, int n_in,
                              void* d_out, int out_size) {
    const float* f = (const float*)d_in[0];
    float* out = (float*)d_out;
    int n = in_sizes[0];

    int blocks = (n + ELEMS_PER_BLOCK - 1) / ELEMS_PER_BLOCK;
    if (blocks > MAX_BLOCKS) blocks = MAX_BLOCKS;   // n <= 64M supported

    k_pass1<<<blocks, TPB>>>(f, n);
    k_sum<<<1, 1024>>>(blocks);
    k_pass2<<<blocks, TPB>>>(f, out, n);
}

// round 3
// speedup vs baseline: 2.0381x; 1.0406x over previous
#include <cuda_runtime.h>

// diff[k] = (f[k-3] - f[k+2]) / 5 with zero-padding outside [0,n)
// change[k] = diff[k]^2 for k>=1, change[0] = 0
// out[k] = (1 - change[k]/S)^5 * f[k],  S = sum(change)

#define TPB 256
#define VPT 6                              // float4 vectors per thread
#define ELEMS_PER_BLOCK (TPB * VPT * 4)    // 6144
#define MAX_BLOCKS 16384
#define FULL 0xffffffffu

__device__ float g_part[MAX_BLOCKS];
__device__ float g_invS;

// Get halo values for the float4 at v (=4*global_thread_vec_index) owned by
// this lane, via intra-warp shuffles; warp-edge lanes fall back to LDG.
// Caller guarantees v-3 >= 0 and v+5 < n on this path.
__device__ __forceinline__ void halo_shfl(const float* __restrict__ f, int v,
                                          float4 c, int lane,
                                          float& m3, float& m2, float& m1,
                                          float& p4, float& p5) {
    m3 = __shfl_up_sync(FULL, c.y, 1);
    m2 = __shfl_up_sync(FULL, c.z, 1);
    m1 = __shfl_up_sync(FULL, c.w, 1);
    p4 = __shfl_down_sync(FULL, c.x, 1);
    p5 = __shfl_down_sync(FULL, c.y, 1);
    if (lane == 0) {
        m3 = __ldg(f + v - 3);
        m2 = __ldg(f + v - 2);
        m1 = __ldg(f + v - 1);
    }
    if (lane == 31) {
        p4 = __ldg(f + v + 4);
        p5 = __ldg(f + v + 5);
    }
}

// ---------------------------------------------------------------- pass 1
__global__ __launch_bounds__(TPB) void k_pass1(const float* __restrict__ f, int n) {
    const int tid  = threadIdx.x;
    const int bid  = blockIdx.x;
    const int lane = tid & 31;
    const int base = bid * ELEMS_PER_BLOCK;
    const bool interior = (bid > 0) && (base + ELEMS_PER_BLOCK + 5 <= n);

    float acc = 0.0f;

    if (interior) {
        #pragma unroll
        for (int j = 0; j < VPT; j++) {
            const int v = base + j * (TPB * 4) + tid * 4;
            float4 c = __ldg(reinterpret_cast<const float4*>(f + v));
            float m3, m2, m1, p4, p5;
            halo_shfl(f, v, c, lane, m3, m2, m1, p4, p5);
            float d0 = (m3  - c.z) * 0.2f;
            float d1 = (m2  - c.w) * 0.2f;
            float d2 = (m1  - p4 ) * 0.2f;
            float d3 = (c.x - p5 ) * 0.2f;
            acc += d0 * d0 + d1 * d1 + d2 * d2 + d3 * d3;
        }
    } else {
        #pragma unroll
        for (int j = 0; j < VPT; j++) {
            const int v = base + j * (TPB * 4) + tid * 4;
            if (v + 3 < n) {
                float4 c = __ldg(reinterpret_cast<const float4*>(f + v));
                float m3 = (v >= 3)     ? __ldg(f + v - 3) : 0.0f;
                float m2 = (v >= 2)     ? __ldg(f + v - 2) : 0.0f;
                float m1 = (v >= 1)     ? __ldg(f + v - 1) : 0.0f;
                float p4 = (v + 4 < n)  ? __ldg(f + v + 4) : 0.0f;
                float p5 = (v + 5 < n)  ? __ldg(f + v + 5) : 0.0f;
                float d0 = (m3  - c.z) * 0.2f;
                float d1 = (m2  - c.w) * 0.2f;
                float d2 = (m1  - p4 ) * 0.2f;
                float d3 = (c.x - p5 ) * 0.2f;
                float c0 = (v == 0) ? 0.0f : d0 * d0;
                acc += c0 + d1 * d1 + d2 * d2 + d3 * d3;
            } else if (v < n) {
                for (int k = v; k < n; k++) {
                    float l = (k >= 3)    ? __ldg(f + k - 3) : 0.0f;
                    float r = (k + 2 < n) ? __ldg(f + k + 2) : 0.0f;
                    float d = (l - r) * 0.2f;
                    if (k != 0) acc += d * d;
                }
            }
        }
    }

    #pragma unroll
    for (int o = 16; o > 0; o >>= 1)
        acc += __shfl_down_sync(FULL, acc, o);

    __shared__ float smem[TPB / 32];
    const int warp = tid >> 5;
    if (lane == 0) smem[warp] = acc;
    __syncthreads();
    if (tid == 0) {
        float b = 0.0f;
        #pragma unroll
        for (int w = 0; w < TPB / 32; w++) b += smem[w];
        g_part[bid] = b;   // plain overwrite: deterministic across graph replays
    }
}

// ---------------------------------------------------------------- sum
__global__ void k_sum(int nblocks) {
    __shared__ double smem[32];
    double acc = 0.0;
    for (int i = threadIdx.x; i < nblocks; i += blockDim.x)
        acc += (double)g_part[i];
    #pragma unroll
    for (int o = 16; o > 0; o >>= 1)
        acc += __shfl_down_sync(FULL, acc, o);
    const int lane = threadIdx.x & 31;
    const int warp = threadIdx.x >> 5;
    if (lane == 0) smem[warp] = acc;
    __syncthreads();
    if (threadIdx.x == 0) {
        double s = 0.0;
        const int nw = blockDim.x / 32;
        for (int w = 0; w < nw; w++) s += smem[w];
        g_invS = (float)(1.0 / s);
    }
}

// ---------------------------------------------------------------- pass 2
__global__ __launch_bounds__(TPB) void k_pass2(const float* __restrict__ f,
                                               float* __restrict__ out, int n) {
    const int tid  = threadIdx.x;
    const int bid  = blockIdx.x;
    const int lane = tid & 31;
    const int base = bid * ELEMS_PER_BLOCK;
    const bool interior = (bid > 0) && (base + ELEMS_PER_BLOCK + 5 <= n);
    const float invS = g_invS;

    if (interior) {
        #pragma unroll
        for (int j = 0; j < VPT; j++) {
            const int v = base + j * (TPB * 4) + tid * 4;
            float4 c = __ldg(reinterpret_cast<const float4*>(f + v));
            float m3, m2, m1, p4, p5;
            halo_shfl(f, v, c, lane, m3, m2, m1, p4, p5);
            float d0 = (m3  - c.z) * 0.2f;
            float d1 = (m2  - c.w) * 0.2f;
            float d2 = (m1  - p4 ) * 0.2f;
            float d3 = (c.x - p5 ) * 0.2f;
            float t0 = 1.0f - d0 * d0 * invS;
            float t1 = 1.0f - d1 * d1 * invS;
            float t2 = 1.0f - d2 * d2 * invS;
            float t3 = 1.0f - d3 * d3 * invS;
            float q0 = t0 * t0, q1 = t1 * t1, q2 = t2 * t2, q3 = t3 * t3;
            float4 o;
            o.x = q0 * q0 * t0 * c.x;
            o.y = q1 * q1 * t1 * c.y;
            o.z = q2 * q2 * t2 * c.z;
            o.w = q3 * q3 * t3 * c.w;
            __stcs(reinterpret_cast<float4*>(out + v), o);
        }
    } else {
        #pragma unroll
        for (int j = 0; j < VPT; j++) {
            const int v = base + j * (TPB * 4) + tid * 4;
            if (v + 3 < n) {
                float4 c = __ldg(reinterpret_cast<const float4*>(f + v));
                float m3 = (v >= 3)    ? __ldg(f + v - 3) : 0.0f;
                float m2 = (v >= 2)    ? __ldg(f + v - 2) : 0.0f;
                float m1 = (v >= 1)    ? __ldg(f + v - 1) : 0.0f;
                float p4 = (v + 4 < n) ? __ldg(f + v + 4) : 0.0f;
                float p5 = (v + 5 < n) ? __ldg(f + v + 5) : 0.0f;
                float d0 = (m3  - c.z) * 0.2f;
                float d1 = (m2  - c.w) * 0.2f;
                float d2 = (m1  - p4 ) * 0.2f;
                float d3 = (c.x - p5 ) * 0.2f;
                float c0 = (v == 0) ? 0.0f : d0 * d0 * invS;
                float t0 = 1.0f - c0;
                float t1 = 1.0f - d1 * d1 * invS;
                float t2 = 1.0f - d2 * d2 * invS;
                float t3 = 1.0f - d3 * d3 * invS;
                float q0 = t0 * t0, q1 = t1 * t1, q2 = t2 * t2, q3 = t3 * t3;
                float4 o;
                o.x = q0 * q0 * t0 * c.x;
                o.y = q1 * q1 * t1 * c.y;
                o.z = q2 * q2 * t2 * c.z;
                o.w = q3 * q3 * t3 * c.w;
                __stcs(reinterpret_cast<float4*>(out + v), o);
            } else if (v < n) {
                for (int k = v; k < n; k++) {
                    float l = (k >= 3)    ? __ldg(f + k - 3) : 0.0f;
                    float r = (k + 2 < n) ? __ldg(f + k + 2) : 0.0f;
                    float d = (l - r) * 0.2f;
                    float ch = (k == 0) ? 0.0f : d * d * invS;
                    float t = 1.0f - ch;
                    float q = t * t;
                    out[k] = q * q * t * __ldg(f + k);
                }
            }
        }
    }
}

// ---------------------------------------------------------------- launch
extern "C" void kernel_launch(void* const* d_in, const int* in_sizes, int n_in,
                              void* d_out, int out_size) {
    const float* f = (const float*)d_in[0];
    float* out = (float*)d_out;
    int n = in_sizes[0];

    int blocks = (n + ELEMS_PER_BLOCK - 1) / ELEMS_PER_BLOCK;
    if (blocks > MAX_BLOCKS) blocks = MAX_BLOCKS;

    k_pass1<<<blocks, TPB>>>(f, n);
    k_sum<<<1, 1024>>>(blocks);
    k_pass2<<<blocks, TPB>>>(f, out, n);
}